// round 7
// baseline (speedup 1.0000x reference)
#include <cuda_runtime.h>
#include <cuda_bf16.h>
#include <math.h>

// Fixed problem shapes
#define BB      16
#define HH      352
#define WW      1216
#define NN      (HH * WW)          // 428032
#define PP      100000
#define BN      (BB * NN)          // 6848512
#define TYPEIND 5
#define MAXD    40.0f

#define WPB     (NN / 32)          // 13376 selector words per batch
#define WORDS   (BB * WPB)         // 214016 words total
#define TPB     64                 // tiles per batch
#define TILE_W  (WPB / TPB)        // 209 words per tile
#define NTILES  (BB * TPB)         // 1024 tiles = grid size
#define NTH     (NTILES * 256)     // 262144 threads total (fully resident)

// Static scratch (no runtime allocation allowed)
__device__ int      d_inv[NN];            // inverse permutation
__device__ unsigned d_permbits[WORDS];    // selector bits in PERMUTED order
__device__ int      d_tileCnt[NTILES];
__device__ int      d_off16[BB];          // per-batch exclusive offset
__device__ int      d_cum16[BB];          // per-batch inclusive cumsum
__device__ int2     d_cd[BN];             // {global lind, depth bits} compacted
__device__ volatile unsigned d_count = 0; // grid barrier counter

// ---------------------------------------------------------------------------
// Software grid barrier (all 1024 blocks guaranteed resident).
// target = generation * gridDim.x, monotonic within one kernel run.
// ---------------------------------------------------------------------------
__device__ __forceinline__ void gridbar(unsigned target) {
    __syncthreads();
    if (threadIdx.x == 0) {
        __threadfence();                       // release prior writes
        atomicAdd((unsigned*)&d_count, 1u);
        while (d_count < target) { }           // volatile L2 poll
        __threadfence();                       // acquire others' writes
    }
    __syncthreads();
}

// ---------------------------------------------------------------------------
// Mega kernel: prep -> select -> count -> prefix+compact -> output
// ---------------------------------------------------------------------------
__global__ void __launch_bounds__(256, 8)
k_mega(const int* __restrict__ label,
       const float* __restrict__ depth,
       const int* __restrict__ perm,
       const float* __restrict__ invK,
       const float* __restrict__ bind,
       float* __restrict__ out) {
    const int t    = threadIdx.x;
    const int blk  = blockIdx.x;
    const int gtid = blk * 256 + t;
    const int lane = t & 31, wid = t >> 5;

    __shared__ int wsA[8];
    __shared__ int wsB[8];
    __shared__ int sBase, sTileTot;

    // ---- Phase 0: zero bit array + build inverse permutation --------------
    for (int i = gtid; i < WORDS; i += NTH) d_permbits[i] = 0u;
    for (int i = gtid; i < NN; i += NTH)    d_inv[perm[i]] = i;
    gridbar(1u * NTILES);

    // ---- Phase 1: selector stream (x4 vectorized, unconditional loads) ----
    for (int qi = gtid; qi < BN / 4; qi += NTH) {
        int gid = qi * 4;
        int4   lab = *reinterpret_cast<const int4*>(label + gid);
        float4 dep = *reinterpret_cast<const float4*>(depth + gid);

        int b       = gid / NN;               // NN % 4 == 0
        int pixBase = gid - b * NN;
        unsigned* pb = d_permbits + b * WPB;

        int labs[4]   = {lab.x, lab.y, lab.z, lab.w};
        float deps[4] = {dep.x, dep.y, dep.z, dep.w};
#pragma unroll
        for (int k = 0; k < 4; k++) {
            if (labs[k] == TYPEIND && deps[k] < MAXD) {
                int j = d_inv[pixBase + k];
                atomicOr(&pb[j >> 5], 1u << (j & 31));
            }
        }
    }
    gridbar(2u * NTILES);

    // ---- Phase 2: count own tile (one word per thread, 209 < 256) ---------
    const int b       = blk / TPB;
    const int wbatch0 = (blk - b * TPB) * TILE_W;
    const int bn      = b * NN;

    unsigned bits = 0;
    if (t < TILE_W) bits = d_permbits[b * WPB + wbatch0 + t];
    int c = __popc(bits);

    {
        int r = c;
#pragma unroll
        for (int off = 16; off; off >>= 1)
            r += __shfl_down_sync(0xffffffffu, r, off);
        if (lane == 0) wsA[wid] = r;
        __syncthreads();
        if (t == 0) {
            int s = 0;
#pragma unroll
            for (int w = 0; w < 8; w++) s += wsA[w];
            d_tileCnt[blk] = s;
            sTileTot = s;
        }
    }
    gridbar(3u * NTILES);

    // ---- Phase 3: global prefix for this tile + compaction ----------------
    {
        int pre = 0;
#pragma unroll
        for (int i = t; i < NTILES; i += 256)
            if (i < blk) pre += d_tileCnt[i];
#pragma unroll
        for (int off = 16; off; off >>= 1)
            pre += __shfl_down_sync(0xffffffffu, pre, off);
        if (lane == 0) wsB[wid] = pre;
        __syncthreads();
        if (t == 0) {
            int s = 0;
#pragma unroll
            for (int w = 0; w < 8; w++) s += wsB[w];
            sBase = s;
        }
        __syncthreads();
    }
    if (t == 0) {
        int tb = blk & (TPB - 1);
        if (tb == 0)       d_off16[blk / TPB] = sBase;
        if (tb == TPB - 1) d_cum16[blk / TPB] = sBase + sTileTot;
    }

    // intra-tile exclusive scan of per-word counts
    int inc = c;
#pragma unroll
    for (int off = 1; off < 32; off <<= 1) {
        int n = __shfl_up_sync(0xffffffffu, inc, off);
        if (lane >= off) inc += n;
    }
    if (lane == 31) wsA[wid] = inc;
    __syncthreads();
    int wbase = 0;
#pragma unroll
    for (int w = 0; w < 8; w++) if (w < wid) wbase += wsA[w];

    int slot = sBase + wbase + inc - c;
    if (bits) {
        int jbase = (wbatch0 + t) * 32;
        unsigned m = bits;
        while (m) {
            int l = __ffs(m) - 1;
            m &= m - 1;
            int pix = __ldg(perm + jbase + l);
            int val = bn + pix;
            float dv = __ldg(depth + val);
            d_cd[slot] = make_int2(val, __float_as_int(dv));
            slot++;
        }
    }
    gridbar(4u * NTILES);

    // ---- Phase 4: sample + back-project + indicator -----------------------
    if (gtid < BB)
        out[3 * BB * PP + gtid] = (d_cum16[gtid] - d_off16[gtid] > 0) ? 1.0f : 0.0f;

    for (int i = gtid; i < BB * PP; i += NTH) {
        int bo = i / PP;
        int p  = i - bo * PP;
        int off = d_off16[bo];
        int vn  = d_cum16[bo] - off;

        int idx = 0;
        if (vn > 0)
            idx = (int)fmodf(bind[i], (float)vn) + off;

        int2  cd  = d_cd[idx];
        int   pos = cd.x;
        float d   = __int_as_float(cd.y);
        int bb2 = pos / NN;
        int pix = pos - bb2 * NN;
        int q   = pix / WW;
        float y = (float)q;
        float x = (float)(pix - q * WW);
        float hx = x * d, hy = y * d;

        const float* M = invK + bb2 * 16;
#pragma unroll
        for (int ch = 0; ch < 3; ch++) {
            float v = fmaf(__ldg(&M[ch * 4 + 0]), hx,
                      fmaf(__ldg(&M[ch * 4 + 1]), hy,
                      fmaf(__ldg(&M[ch * 4 + 2]), d, __ldg(&M[ch * 4 + 3]))));
            out[(bo * 3 + ch) * PP + p] = v;
        }
    }
}

// Reset barrier counter for next graph replay (runs after k_mega).
__global__ void k_reset() { d_count = 0; }

// ---------------------------------------------------------------------------
extern "C" void kernel_launch(void* const* d_in, const int* in_sizes, int n_in,
                              void* d_out, int out_size) {
    const float* predDepth = (const float*)d_in[0];   // [B,1,H,W]
    const float* invcamK   = (const float*)d_in[1];   // [B,4,4]
    const int*   semLabel  = (const int*)  d_in[2];   // [B,1,H,W]
    const float* bind      = (const float*)d_in[3];   // [B,P]
    const int*   perm      = (const int*)  d_in[4];   // [N]
    float* out = (float*)d_out;

    k_mega <<<NTILES, 256>>>(semLabel, predDepth, perm, invcamK, bind, out);
    k_reset<<<1, 1>>>();
}

// round 8
// speedup vs baseline: 1.1824x; 1.1824x over previous
#include <cuda_runtime.h>
#include <cuda_bf16.h>
#include <math.h>

// Fixed problem shapes
#define BB      16
#define HH      352
#define WW      1216
#define NN      (HH * WW)          // 428032
#define PP      100000
#define BN      (BB * NN)          // 6848512
#define TYPEIND 5
#define MAXD    40.0f

#define WPB     (NN / 32)          // 13376 selector words per batch
#define WORDS   (BB * WPB)         // 214016 words total
#define TPB     64                 // tiles per batch
#define TILE_W  (WPB / TPB)        // 209 words per tile
#define NTILES  (BB * TPB)         // 1024 tiles
#define TILE_BITS (TILE_W * 32)    // 6688 max entries per tile

// Static scratch (no runtime allocation allowed)
__device__ int      d_inv[NN];            // inverse permutation
__device__ unsigned d_permbits[WORDS];    // selector bits in PERMUTED order
__device__ int      d_tileCnt[NTILES];    // published count+1 (0 = not ready)
__device__ int      d_off16[BB];          // per-batch exclusive offset
__device__ int      d_valid[BB];          // per-batch count
__device__ int2     d_cd[BN];             // {global lind, depth bits} compacted

// ---------------------------------------------------------------------------
// K1: zero bit array + tile flags; build inverse permutation.
// ---------------------------------------------------------------------------
__global__ void k_prep(const int* __restrict__ perm) {
    int gid = blockIdx.x * blockDim.x + threadIdx.x;
    if (gid < WORDS)  d_permbits[gid] = 0u;
    if (gid < NTILES) d_tileCnt[gid] = 0;
    if (gid < NN)     d_inv[perm[gid]] = gid;
}

// ---------------------------------------------------------------------------
// K2: stream selector (x4 vectorized, unconditional loads for MLP).
// Selected pixels (~2.6%) set their permuted bit.
// ---------------------------------------------------------------------------
__global__ void k_select(const int* __restrict__ label,
                         const float* __restrict__ depth) {
    int t   = blockIdx.x * blockDim.x + threadIdx.x;
    int gid = t * 4;                              // BN divisible by 4
    int4   lab = *reinterpret_cast<const int4*>(label + gid);
    float4 dep = *reinterpret_cast<const float4*>(depth + gid);

    int b       = gid / NN;                       // NN % 4 == 0
    int pixBase = gid - b * NN;
    unsigned* pb = d_permbits + b * WPB;

    int labs[4]   = {lab.x, lab.y, lab.z, lab.w};
    float deps[4] = {dep.x, dep.y, dep.z, dep.w};
#pragma unroll
    for (int k = 0; k < 4; k++) {
        if (labs[k] == TYPEIND && deps[k] < MAXD) {
            int j = d_inv[pixBase + k];
            atomicOr(&pb[j >> 5], 1u << (j & 31));
        }
    }
}

// ---------------------------------------------------------------------------
// K3: count + decoupled lookback + load-balanced compaction, one launch.
// grid = NTILES x 256, fully resident (8 blocks/SM cap via launch bounds).
// ---------------------------------------------------------------------------
__global__ void __launch_bounds__(256, 8)
k_compact(const int* __restrict__ perm,
          const float* __restrict__ depth) {
    const int blk  = blockIdx.x;
    const int t    = threadIdx.x;
    const int lane = t & 31, wid = t >> 5;

    __shared__ int sj[TILE_BITS];     // staged j-positions (26.8 KB)
    __shared__ int wsA[8];
    __shared__ int sTot, sBase;

    const int b       = blk / TPB;
    const int wbatch0 = (blk - b * TPB) * TILE_W;
    const int bn      = b * NN;

    // --- count own tile ---
    unsigned bits = 0;
    if (t < TILE_W) bits = d_permbits[b * WPB + wbatch0 + t];
    int c = __popc(bits);

    {
        int r = c;
#pragma unroll
        for (int off = 16; off; off >>= 1)
            r += __shfl_down_sync(0xffffffffu, r, off);
        if (lane == 0) wsA[wid] = r;
        __syncthreads();
        if (t == 0) {
            int s = 0;
#pragma unroll
            for (int w = 0; w < 8; w++) s += wsA[w];
            sTot = s;
            // publish count (flag = +1) BEFORE waiting on predecessors
            __threadfence();
            *((volatile int*)&d_tileCnt[blk]) = s + 1;
        }
        __syncthreads();
    }

    // --- lookback: sum predecessor counts (<=4 polls per thread) ---
    {
        int pre = 0;
        for (int i = t; i < blk; i += 256) {
            int v;
            while ((v = *((volatile int*)&d_tileCnt[i])) == 0) { }
            pre += v - 1;
        }
#pragma unroll
        for (int off = 16; off; off >>= 1)
            pre += __shfl_down_sync(0xffffffffu, pre, off);
        if (lane == 0) wsA[wid] = pre;
        __syncthreads();
        if (t == 0) {
            int s = 0;
#pragma unroll
            for (int w = 0; w < 8; w++) s += wsA[w];
            sBase = s;
            // per-batch stats from boundary tiles
            int tb = blk & (TPB - 1);
            if (tb == 0)       d_off16[b] = s;
            if (tb == TPB - 1) d_valid[b] = s + sTot - 0;   // cum; fixed below
        }
        __syncthreads();
    }
    // NOTE: d_valid currently holds inclusive cum for batch b written by its
    // last tile; k_output computes valid = cum - off. To keep one array name
    // honest we store cum here and subtract in output.

    // --- stage set-bit positions into smem (cheap ALU, balanced later) ---
    {
        int inc = c;
#pragma unroll
        for (int off = 1; off < 32; off <<= 1) {
            int n = __shfl_up_sync(0xffffffffu, inc, off);
            if (lane >= off) inc += n;
        }
        __shared__ int wsB[8];
        if (lane == 31) wsB[wid] = inc;
        __syncthreads();
        int wbase = 0;
#pragma unroll
        for (int w = 0; w < 8; w++) if (w < wid) wbase += wsB[w];
        int ofs = wbase + inc - c;
        unsigned m = bits;
        int jbase = (wbatch0 + t) * 32;
        while (m) {
            int l = __ffs(m) - 1;
            m &= m - 1;
            sj[ofs++] = jbase + l;
        }
        __syncthreads();
    }

    // --- balanced gather + coalesced store ---
    int tot = sTot, base = sBase;
    for (int i = t; i < tot; i += 256) {
        int j   = sj[i];
        int pix = __ldg(perm + j);
        int val = bn + pix;
        float dv = __ldg(depth + val);
        d_cd[base + i] = make_int2(val, __float_as_int(dv));
    }
}

// ---------------------------------------------------------------------------
// K4: sample + back-project, 2 points per thread; write [B,3,P] + [B] ind.
// ---------------------------------------------------------------------------
__global__ void k_output(const float* __restrict__ invK,
                         const float* __restrict__ bind,
                         float* __restrict__ out) {
    int gtid = blockIdx.x * blockDim.x + threadIdx.x;
    if (gtid < BB) {
        int vn = d_valid[gtid] - d_off16[gtid];
        out[3 * BB * PP + gtid] = (vn > 0) ? 1.0f : 0.0f;
    }
    int i0 = gtid * 2;                           // BB*PP even
    if (i0 >= BB * PP) return;

    int b   = i0 / PP;                           // PP even -> same batch pair
    int p   = i0 - b * PP;
    int off = d_off16[b];
    int vn  = d_valid[b] - off;

    float2 bv = *reinterpret_cast<const float2*>(bind + i0);

    int idx0 = 0, idx1 = 0;
    if (vn > 0) {
        float fvn = (float)vn;
        idx0 = (int)fmodf(bv.x, fvn) + off;
        idx1 = (int)fmodf(bv.y, fvn) + off;
    }

    int2 cd0 = d_cd[idx0];
    int2 cd1 = d_cd[idx1];

    const float* M = invK + b * 16;
    float m00 = __ldg(&M[0]),  m01 = __ldg(&M[1]),  m02 = __ldg(&M[2]),  m03 = __ldg(&M[3]);
    float m10 = __ldg(&M[4]),  m11 = __ldg(&M[5]),  m12 = __ldg(&M[6]),  m13 = __ldg(&M[7]);
    float m20 = __ldg(&M[8]),  m21 = __ldg(&M[9]),  m22 = __ldg(&M[10]), m23 = __ldg(&M[11]);

#pragma unroll
    for (int k = 0; k < 2; k++) {
        int2  cd = k ? cd1 : cd0;
        int   pos = cd.x;
        float d   = __int_as_float(cd.y);
        int bb2 = pos / NN;
        int pix = pos - bb2 * NN;
        int q   = pix / WW;
        float y = (float)q;
        float x = (float)(pix - q * WW);
        float hx = x * d, hy = y * d;
        // bb2 may differ from b only if cross-batch leakage existed (it
        // doesn't: compaction is per-batch), so reuse b's matrix rows.
        float v0 = fmaf(m00, hx, fmaf(m01, hy, fmaf(m02, d, m03)));
        float v1 = fmaf(m10, hx, fmaf(m11, hy, fmaf(m12, d, m13)));
        float v2 = fmaf(m20, hx, fmaf(m21, hy, fmaf(m22, d, m23)));
        out[(b * 3 + 0) * PP + p + k] = v0;
        out[(b * 3 + 1) * PP + p + k] = v1;
        out[(b * 3 + 2) * PP + p + k] = v2;
    }
}

// ---------------------------------------------------------------------------
extern "C" void kernel_launch(void* const* d_in, const int* in_sizes, int n_in,
                              void* d_out, int out_size) {
    const float* predDepth = (const float*)d_in[0];   // [B,1,H,W]
    const float* invcamK   = (const float*)d_in[1];   // [B,4,4]
    const int*   semLabel  = (const int*)  d_in[2];   // [B,1,H,W]
    const float* bind      = (const float*)d_in[3];   // [B,P]
    const int*   perm      = (const int*)  d_in[4];   // [N]
    float* out = (float*)d_out;

    k_prep   <<<NN / 256, 256>>>(perm);
    k_select <<<BN / 1024, 256>>>(semLabel, predDepth);
    k_compact<<<NTILES, 256>>>(perm, predDepth);
    k_output <<<(BB * PP / 2 + 255) / 256, 256>>>(invcamK, bind, out);
}